// round 13
// baseline (speedup 1.0000x reference)
#include <cuda_runtime.h>
#include <cuda_fp16.h>
#include <math.h>
#include <stdint.h>

#define N_NODES 8192
#define NW 64
#define SPLITK 32
#define KSLICE (N_NODES / SPLITK)   // 256
#define BM 128
#define NSTEP (KSLICE / 16)         // 16 k16-steps
// fragment-packed B smem: [st][lane][nt] uint2, lane stride 80B (64B data + 16B pad)
#define BFRAG_LANE 80
#define BFRAG_ST (32 * BFRAG_LANE)        // 2560
#define BFRAG_BYTES (16 * BFRAG_ST)       // 40960
#define JTAB_OFF BFRAG_BYTES
#define FUSED_SMEM (BFRAG_BYTES + 1024)   // + 64 x 16B j-table
// global fragment Xt: [kq][st][lane][nt] dense, 16384 halfs per kq
#define XT_KQ_HALFS 16384

// ---------------- scratch (device globals) ----------------
__device__ float    g_Zp[SPLITK][N_NODES];
__device__ float    g_X1f[N_NODES * NW];
__device__ __align__(16) __half g_X1t[N_NODES * NW];   // fragment-packed
__device__ float    g_X2f[N_NODES * NW];
__device__ __align__(16) __half g_X2t[N_NODES * NW];   // fragment-packed
__device__ uint32_t g_Yph[SPLITK][N_NODES * 32];       // half2 split-K GEMM partials (32MB)
__device__ __align__(16) float2 g_eps[N_NODES];        // prescaled (sc*eta, sc*phi)
__device__ float    g_sp[256 * NW];

__device__ __forceinline__ void cpa16(uint32_t dst, const void* src) {
    asm volatile("cp.async.cg.shared.global [%0], [%1], 16;\n" :: "r"(dst), "l"(src));
}
__device__ __forceinline__ uint32_t smem_u32(const void* p) {
    uint32_t a;
    asm("{ .reg .u64 t; cvta.to.shared.u64 t, %1; cvt.u32.u64 %0, t; }" : "=r"(a) : "l"(p));
    return a;
}
__device__ __forceinline__ uint32_t cvt_h2(float lo, float hi) {
    uint32_t d;
    asm("cvt.rn.f16x2.f32 %0, %1, %2;" : "=r"(d) : "f"(hi), "f"(lo));
    return d;
}
__device__ __forceinline__ uint32_t ex2_h2(uint32_t a) {
    uint32_t d; asm("ex2.approx.f16x2 %0, %1;" : "=r"(d) : "r"(a)); return d;
}
__device__ __forceinline__ __half2 u2h(uint32_t u) { return *reinterpret_cast<__half2*>(&u); }
// position of logical k (0..15) inside a permuted 16-group
__device__ __forceinline__ int kperm(int k) {
    return (((k & 6) + (k >> 3)) << 1) + (k & 1);
}
// half-index of element (n, k) in the fragment-packed global Xt
__device__ __forceinline__ size_t xt_idx(int n, int k) {
    int kq = k >> 8, kin = k & 255;
    int st = kin >> 4, p = kperm(kin & 15);
    int lane = ((n & 7) << 2) | (p >> 2);
    int nt = n >> 3;
    return ((((size_t)kq * 16 + st) * 32 + lane) * 8 + nt) * 4 + (p & 3);
}

// ---------------- K0: X1 = relu(x@W1+b1), prescaled (eta,phi), fragment-packed X1t ----------------
__global__ void prep_kernel(const float* __restrict__ x, const float* __restrict__ W1,
                            const float* __restrict__ b1, const float* __restrict__ alpha_p) {
    int row = blockIdx.x * 4 + (threadIdx.x >> 6);
    int n = threadIdx.x & 63;
    float acc = b1[n];
#pragma unroll
    for (int k = 0; k < 7; k++) acc += x[row * 7 + k] * W1[k * NW + n];
    acc = fmaxf(acc, 0.0f);
    g_X1f[row * NW + n] = acc;
    g_X1t[xt_idx(n, row)] = __float2half(acc);
    if (n == 0) {
        const float L2E = 1.4426950408889634f;
        float sc = sqrtf(alpha_p[0] * L2E);
        g_eps[row] = make_float2(sc * x[row * 7 + 1], sc * x[row * 7 + 2]);
    }
}

// ---------------- fused GEMM: half2 E-args, f16 acc, Z via ones-MMA ----------------
// grid: 64 rtiles x 32 kq. Block 256 = 8 warps, each warp owns 16 rows.
__global__ __launch_bounds__(256, 5) void fused_gemm_kernel(int which,
                                                            const float* __restrict__ alpha_p) {
    extern __shared__ char smem[];
    const __half* __restrict__ Xt = which ? g_X2t : g_X1t;

    int tid = threadIdx.x, lane = tid & 31, warp = tid >> 5;
    int rtile = blockIdx.x >> 5, kq = blockIdx.x & 31;
    int rbase = rtile * BM, kbeg = kq * KSLICE;

    const float L2E = 1.4426950408889634f;
    float sc = sqrtf(alpha_p[0] * L2E);
    const float C = 0.5287663729448977f;    // log2(log2 e)
    float wrapc = sc * 6.283185307179586f;  // scaled 2*pi

    uint32_t sb_base = smem_u32(smem);

    // ---- stage fragment-packed B slice: 2048 coalesced 16B chunks ----
    {
        const char* src_base = (const char*)(Xt + (size_t)kq * XT_KQ_HALFS);
#pragma unroll
        for (int it = 0; it < 8; it++) {
            int c = tid + it * 256;             // 2048 chunks
            int st = c >> 7, ln = (c >> 2) & 31, piece = c & 3;
            uint32_t dst = sb_base + st * BFRAG_ST + ln * BFRAG_LANE + piece * 16;
            cpa16(dst, src_base + (size_t)c * 16);
        }
        asm volatile("cp.async.commit_group;\n" ::: "memory");
        // j-table: [st][ch] = {ej0, pj0, ej1, pj1} (16B)
        if (tid < 64) {
            int st = tid >> 2, ch = tid & 3;
            const float2* jp = g_eps + kbeg + st * 16 + ch * 2;
            float2 ja = jp[0], jb = jp[1], jc = jp[4], jd = jp[5];
            uint4 v;
            v.x = cvt_h2(ja.x, jb.x);
            v.y = cvt_h2(ja.y, jb.y);
            v.z = cvt_h2(jc.x, jd.x);
            v.w = cvt_h2(jc.y, jd.y);
            *reinterpret_cast<uint4*>(smem + JTAB_OFF + tid * 16) = v;
        }
        asm volatile("cp.async.wait_group 0;\n" ::: "memory");
        __syncthreads();
    }

    int r = lane >> 2;
    int row0 = rbase + warp * 16 + r;
    float2 v0 = g_eps[row0];
    float2 v1 = g_eps[row0 + 8];
    __half2 er0b = __half2half2(__float2half(v0.x));
    __half2 pr0b = __half2half2(__float2half(v0.y));
    __half2 er1b = __half2half2(__float2half(v1.x));
    __half2 pr1b = __half2half2(__float2half(v1.y));
    __half2 wrap2 = __half2half2(__float2half(wrapc));
    __half2 C2 = __half2half2(__float2half(C));

    int ch = lane & 3;

    uint32_t acc[8][2];
#pragma unroll
    for (int nt = 0; nt < 8; nt++) { acc[nt][0] = 0u; acc[nt][1] = 0u; }
    float accZ[4] = {0.f, 0.f, 0.f, 0.f};
    const uint32_t BONE = 0x3C003C00u;      // half2(1,1)

    const uint4* sJ4 = reinterpret_cast<const uint4*>(smem + JTAB_OFF);
    const char* bfp = smem + lane * BFRAG_LANE;

#pragma unroll 2
    for (int st = 0; st < NSTEP; st++) {
        uint4 jj = sJ4[st * 4 + ch];
        __half2 ej0 = u2h(jj.x), pj0 = u2h(jj.y);
        __half2 ej1 = u2h(jj.z), pj1 = u2h(jj.w);

        uint32_t a0, a1, a2, a3;
        {
            __half2 de = __hsub2(er0b, ej0);
            __half2 dpa = __habs2(__hsub2(pr0b, pj0));
            __half2 dpm = __hmin2(dpa, __hsub2(wrap2, dpa));
            __half2 t = __hfma2(de, de, __hmul2(dpm, dpm));
            __half2 arg = __hsub2(C2, t);
            a0 = ex2_h2(ex2_h2(*reinterpret_cast<uint32_t*>(&arg)));
        }
        {
            __half2 de = __hsub2(er1b, ej0);
            __half2 dpa = __habs2(__hsub2(pr1b, pj0));
            __half2 dpm = __hmin2(dpa, __hsub2(wrap2, dpa));
            __half2 t = __hfma2(de, de, __hmul2(dpm, dpm));
            __half2 arg = __hsub2(C2, t);
            a1 = ex2_h2(ex2_h2(*reinterpret_cast<uint32_t*>(&arg)));
        }
        {
            __half2 de = __hsub2(er0b, ej1);
            __half2 dpa = __habs2(__hsub2(pr0b, pj1));
            __half2 dpm = __hmin2(dpa, __hsub2(wrap2, dpa));
            __half2 t = __hfma2(de, de, __hmul2(dpm, dpm));
            __half2 arg = __hsub2(C2, t);
            a2 = ex2_h2(ex2_h2(*reinterpret_cast<uint32_t*>(&arg)));
        }
        {
            __half2 de = __hsub2(er1b, ej1);
            __half2 dpa = __habs2(__hsub2(pr1b, pj1));
            __half2 dpm = __hmin2(dpa, __hsub2(wrap2, dpa));
            __half2 t = __hfma2(de, de, __hmul2(dpm, dpm));
            __half2 arg = __hsub2(C2, t);
            a3 = ex2_h2(ex2_h2(*reinterpret_cast<uint32_t*>(&arg)));
        }

        // Z via ones-B MMA (fp32 accumulate, exact row sums)
        asm volatile(
            "mma.sync.aligned.m16n8k16.row.col.f32.f16.f16.f32 "
            "{%0,%1,%2,%3}, {%4,%5,%6,%7}, {%8,%9}, {%0,%1,%2,%3};"
            : "+f"(accZ[0]), "+f"(accZ[1]), "+f"(accZ[2]), "+f"(accZ[3])
            : "r"(a0), "r"(a1), "r"(a2), "r"(a3), "r"(BONE), "r"(BONE));

        const uint4* bs = reinterpret_cast<const uint4*>(bfp + st * BFRAG_ST);
#pragma unroll
        for (int g = 0; g < 4; g++) {
            uint4 bb = bs[g];       // nt=2g -> (x,y); nt=2g+1 -> (z,w)
            asm volatile(
                "mma.sync.aligned.m16n8k16.row.col.f16.f16.f16.f16 "
                "{%0,%1}, {%2,%3,%4,%5}, {%6,%7}, {%0,%1};"
                : "+r"(acc[2 * g][0]), "+r"(acc[2 * g][1])
                : "r"(a0), "r"(a1), "r"(a2), "r"(a3), "r"(bb.x), "r"(bb.y));
            asm volatile(
                "mma.sync.aligned.m16n8k16.row.col.f16.f16.f16.f16 "
                "{%0,%1}, {%2,%3,%4,%5}, {%6,%7}, {%0,%1};"
                : "+r"(acc[2 * g + 1][0]), "+r"(acc[2 * g + 1][1])
                : "r"(a0), "r"(a1), "r"(a2), "r"(a3), "r"(bb.z), "r"(bb.w));
        }
    }

    // ---- Z partials: every lane in a quad holds identical col values ----
    if ((lane & 3) == 0) {
        g_Zp[kq][row0] = accZ[0];
        g_Zp[kq][row0 + 8] = accZ[2];
    }

    // ---- epilogue: acc already half2 partials ----
    uint32_t* Yp = g_Yph[kq];
    int cp = lane & 3;
#pragma unroll
    for (int nt = 0; nt < 8; nt++) {
        Yp[(size_t)row0 * 32 + nt * 4 + cp] = acc[nt][0];
        Yp[(size_t)(row0 + 8) * 32 + nt * 4 + cp] = acc[nt][1];
    }
}

// ---------------- mid: combine + V1=relu(Y@wt1+bs1) + X2=relu(V1@W2+b2) ----------------
// 256 blocks x 32 rows
#define MID_SMEM ((4096 * 2 + 2048 + 32) * 4)
__global__ __launch_bounds__(256) void mid_kernel(const float* __restrict__ wt1,
                                                  const float* __restrict__ bs1,
                                                  const float* __restrict__ W2,
                                                  const float* __restrict__ b2) {
    extern __shared__ float sm[];
    float* s_w1 = sm;
    float* s_w2 = sm + 4096;
    float* s_y  = sm + 8192;
    float* s_zi = sm + 8192 + 2048;
    int tid = threadIdx.x;
    int r0 = blockIdx.x * 32;

    for (int i = tid; i < 4096; i += 256) { s_w1[i] = wt1[i]; s_w2[i] = W2[i]; }
    if (tid < 32) {
        float zs = 0.f;
#pragma unroll
        for (int p = 0; p < SPLITK; p++) zs += g_Zp[p][r0 + tid];
        s_zi[tid] = 1.0f / zs;
    }
    __syncthreads();

    const float4* X4 = reinterpret_cast<const float4*>(g_X1f + (size_t)r0 * NW);
#pragma unroll
    for (int it = 0; it < 2; it++) {
        int i = tid + it * 256;             // 512 float4 = 32 rows x 16
        float4 v = make_float4(0.f, 0.f, 0.f, 0.f);
#pragma unroll
        for (int p = 0; p < SPLITK; p++) {
            uint2 u = reinterpret_cast<const uint2*>(g_Yph[p] + (size_t)r0 * 32)[i];
            float2 fa = __half22float2(*reinterpret_cast<__half2*>(&u.x));
            float2 fb = __half22float2(*reinterpret_cast<__half2*>(&u.y));
            v.x += fa.x; v.y += fa.y; v.z += fb.x; v.w += fb.y;
        }
        float zi = s_zi[i >> 4];
        float4 xv = X4[i];
        reinterpret_cast<float4*>(s_y)[i] =
            make_float4(fmaf(v.x, zi, xv.x), fmaf(v.y, zi, xv.y),
                        fmaf(v.z, zi, xv.z), fmaf(v.w, zi, xv.w));
    }
    __syncthreads();

    int cgp = tid & 15, rg = tid >> 4;
    int c0 = cgp * 4, rl0 = rg * 2;
    float bsv = bs1[0];
    float acc[2][4];
#pragma unroll
    for (int rr = 0; rr < 2; rr++)
#pragma unroll
        for (int c = 0; c < 4; c++) acc[rr][c] = bsv;
#pragma unroll 8
    for (int k = 0; k < 64; k++) {
        float4 w = reinterpret_cast<const float4*>(s_w1 + k * 64)[cgp];
#pragma unroll
        for (int rr = 0; rr < 2; rr++) {
            float y = s_y[(rl0 + rr) * 64 + k];
            acc[rr][0] = fmaf(y, w.x, acc[rr][0]);
            acc[rr][1] = fmaf(y, w.y, acc[rr][1]);
            acc[rr][2] = fmaf(y, w.z, acc[rr][2]);
            acc[rr][3] = fmaf(y, w.w, acc[rr][3]);
        }
    }
    __syncthreads();
#pragma unroll
    for (int rr = 0; rr < 2; rr++)
        reinterpret_cast<float4*>(s_y + (rl0 + rr) * 64)[cgp] =
            make_float4(fmaxf(acc[rr][0], 0.f), fmaxf(acc[rr][1], 0.f),
                        fmaxf(acc[rr][2], 0.f), fmaxf(acc[rr][3], 0.f));
    __syncthreads();

    float4 bz = *reinterpret_cast<const float4*>(b2 + c0);
#pragma unroll
    for (int rr = 0; rr < 2; rr++) { acc[rr][0] = bz.x; acc[rr][1] = bz.y; acc[rr][2] = bz.z; acc[rr][3] = bz.w; }
#pragma unroll 8
    for (int k = 0; k < 64; k++) {
        float4 w = reinterpret_cast<const float4*>(s_w2 + k * 64)[cgp];
#pragma unroll
        for (int rr = 0; rr < 2; rr++) {
            float y = s_y[(rl0 + rr) * 64 + k];
            acc[rr][0] = fmaf(y, w.x, acc[rr][0]);
            acc[rr][1] = fmaf(y, w.y, acc[rr][1]);
            acc[rr][2] = fmaf(y, w.z, acc[rr][2]);
            acc[rr][3] = fmaf(y, w.w, acc[rr][3]);
        }
    }
#pragma unroll
    for (int rr = 0; rr < 2; rr++)
#pragma unroll
        for (int c = 0; c < 4; c++) acc[rr][c] = fmaxf(acc[rr][c], 0.f);

#pragma unroll
    for (int rr = 0; rr < 2; rr++)
        *reinterpret_cast<float4*>(g_X2f + (size_t)(r0 + rl0 + rr) * NW + c0) =
            make_float4(acc[rr][0], acc[rr][1], acc[rr][2], acc[rr][3]);

    // fragment-packed transposed write: rows rl0, rl0+1 (even pair -> same uint2 slot pair)
    {
        int base_row = r0 + rl0;
#pragma unroll
        for (int c = 0; c < 4; c++) {
            __half2 h01 = __floats2half2_rn(acc[0][c], acc[1][c]);
            *reinterpret_cast<__half2*>(g_X2t + xt_idx(c0 + c, base_row)) = h01;
        }
    }
}

// ---------------- last: combine + V2=relu(Y@wt2+bs2) + column partial sums ----------------
#define LAST_SMEM ((4096 + 2048 + 32 + 1024) * 4)
__global__ __launch_bounds__(256) void last_kernel(const float* __restrict__ wt2,
                                                   const float* __restrict__ bs2) {
    extern __shared__ float sm[];
    float* s_w  = sm;
    float* s_y  = sm + 4096;
    float* s_zi = sm + 4096 + 2048;
    float* s_part = s_zi + 32;
    int tid = threadIdx.x;
    int r0 = blockIdx.x * 32;

    for (int i = tid; i < 4096; i += 256) s_w[i] = wt2[i];
    if (tid < 32) {
        float zs = 0.f;
#pragma unroll
        for (int p = 0; p < SPLITK; p++) zs += g_Zp[p][r0 + tid];
        s_zi[tid] = 1.0f / zs;
    }
    __syncthreads();

    const float4* X4 = reinterpret_cast<const float4*>(g_X2f + (size_t)r0 * NW);
#pragma unroll
    for (int it = 0; it < 2; it++) {
        int i = tid + it * 256;
        float4 v = make_float4(0.f, 0.f, 0.f, 0.f);
#pragma unroll
        for (int p = 0; p < SPLITK; p++) {
            uint2 u = reinterpret_cast<const uint2*>(g_Yph[p] + (size_t)r0 * 32)[i];
            float2 fa = __half22float2(*reinterpret_cast<__half2*>(&u.x));
            float2 fb = __half22float2(*reinterpret_cast<__half2*>(&u.y));
            v.x += fa.x; v.y += fa.y; v.z += fb.x; v.w += fb.y;
        }
        float zi = s_zi[i >> 4];
        float4 xv = X4[i];
        reinterpret_cast<float4*>(s_y)[i] =
            make_float4(fmaf(v.x, zi, xv.x), fmaf(v.y, zi, xv.y),
                        fmaf(v.z, zi, xv.z), fmaf(v.w, zi, xv.w));
    }
    __syncthreads();

    int cgp = tid & 15, rg = tid >> 4;
    int c0 = cgp * 4, rl0 = rg * 2;
    float bv = bs2[0];
    float acc[2][4];
#pragma unroll
    for (int rr = 0; rr < 2; rr++)
#pragma unroll
        for (int c = 0; c < 4; c++) acc[rr][c] = bv;
#pragma unroll 8
    for (int k = 0; k < 64; k++) {
        float4 w = reinterpret_cast<const float4*>(s_w + k * 64)[cgp];
#pragma unroll
        for (int rr = 0; rr < 2; rr++) {
            float y = s_y[(rl0 + rr) * 64 + k];
            acc[rr][0] = fmaf(y, w.x, acc[rr][0]);
            acc[rr][1] = fmaf(y, w.y, acc[rr][1]);
            acc[rr][2] = fmaf(y, w.z, acc[rr][2]);
            acc[rr][3] = fmaf(y, w.w, acc[rr][3]);
        }
    }
#pragma unroll
    for (int c = 0; c < 4; c++) {
        float cs = fmaxf(acc[0][c], 0.f) + fmaxf(acc[1][c], 0.f);
        s_part[rg * 64 + c0 + c] = cs;
    }
    __syncthreads();
    if (tid < 64) {
        float t = 0.f;
#pragma unroll
        for (int g = 0; g < 16; g++) t += s_part[g * 64 + tid];
        g_sp[blockIdx.x * NW + tid] = t;
    }
}

// ---------------- final: out = sigmoid(s@Wl + bl) ----------------
__global__ void final_kernel(const float* __restrict__ Wl, const float* __restrict__ bl,
                             float* __restrict__ out) {
    int tid = threadIdx.x;             // 256 threads
    int n = tid & 63, g = tid >> 6;    // 4 chunks of 64 rows
    float s = 0.0f;
    for (int b = g * 64; b < (g + 1) * 64; b++) s += g_sp[b * NW + n];
    __shared__ float sh[256];
    sh[tid] = s;
    __syncthreads();
    if (tid < 64) {
        float t = (sh[tid] + sh[tid + 64] + sh[tid + 128] + sh[tid + 192]) * Wl[tid];
        sh[tid] = t;
    }
    __syncthreads();
    if (tid < 32) {
        float t = sh[tid] + sh[tid + 32];
        for (int o = 16; o; o >>= 1) t += __shfl_down_sync(0xffffffffu, t, o);
        if (tid == 0) out[0] = 1.0f / (1.0f + expf(-(t + bl[0])));
    }
}

// ---------------- launch ----------------
extern "C" void kernel_launch(void* const* d_in, const int* in_sizes, int n_in,
                              void* d_out, int out_size) {
    (void)in_sizes; (void)n_in; (void)out_size;
    const float* x     = (const float*)d_in[0];
    const float* alpha = (const float*)d_in[1];
    const float* W1    = (const float*)d_in[2];
    const float* b1    = (const float*)d_in[3];
    const float* wt1   = (const float*)d_in[4];
    const float* bs1   = (const float*)d_in[5];
    const float* W2    = (const float*)d_in[6];
    const float* b2    = (const float*)d_in[7];
    const float* wt2   = (const float*)d_in[8];
    const float* bs2   = (const float*)d_in[9];
    const float* Wl    = (const float*)d_in[10];
    const float* bl    = (const float*)d_in[11];
    float* out = (float*)d_out;

    cudaFuncSetAttribute(fused_gemm_kernel, cudaFuncAttributeMaxDynamicSharedMemorySize, FUSED_SMEM);
    cudaFuncSetAttribute(mid_kernel, cudaFuncAttributeMaxDynamicSharedMemorySize, MID_SMEM);
    cudaFuncSetAttribute(last_kernel, cudaFuncAttributeMaxDynamicSharedMemorySize, LAST_SMEM);

    prep_kernel<<<2048, 256>>>(x, W1, b1, alpha);

    fused_gemm_kernel<<<2048, 256, FUSED_SMEM>>>(0, alpha);
    mid_kernel<<<256, 256, MID_SMEM>>>(wt1, bs1, W2, b2);

    fused_gemm_kernel<<<2048, 256, FUSED_SMEM>>>(1, alpha);
    last_kernel<<<256, 256, LAST_SMEM>>>(wt2, bs2);

    final_kernel<<<1, 256>>>(Wl, bl, out);
}

// round 14
// speedup vs baseline: 1.4223x; 1.4223x over previous
#include <cuda_runtime.h>
#include <cuda_fp16.h>
#include <math.h>
#include <stdint.h>

#define N_NODES 8192
#define NW 64
#define SPLITK 32
#define KSLICE (N_NODES / SPLITK)   // 256
#define BM 128
#define NSTEP (KSLICE / 16)         // 16 k16-steps
#define BSTRIDE 272                 // halfs per B smem row (256 + 16) -> 8-bank shift/row
#define BSMEM (64 * BSTRIDE * 2)    // 34816 bytes
#define FUSED_SMEM (BSMEM + 1024)   // + 128 j-pairs * 8B (half2 e-pair, p-pair)

// ---------------- scratch (device globals) ----------------
__device__ float    g_Zp[SPLITK][N_NODES];
__device__ float    g_X1f[N_NODES * NW];
__device__ __half   g_X1t[NW * N_NODES];               // k-permuted [n][perm(row)]
__device__ float    g_X2f[N_NODES * NW];
__device__ __half   g_X2t[NW * N_NODES];               // k-permuted
__device__ uint32_t g_Yph[SPLITK][N_NODES * 32];       // half2 split-K GEMM partials (32MB)
__device__ __align__(16) float2 g_eps[N_NODES];        // prescaled (sc*eta, sc*phi)
__device__ float    g_sp[256 * NW];

__device__ __forceinline__ void cpa16(uint32_t dst, const void* src) {
    asm volatile("cp.async.cg.shared.global [%0], [%1], 16;\n" :: "r"(dst), "l"(src));
}
__device__ __forceinline__ uint32_t smem_u32(const void* p) {
    uint32_t a;
    asm("{ .reg .u64 t; cvta.to.shared.u64 t, %1; cvt.u32.u64 %0, t; }" : "=r"(a) : "l"(p));
    return a;
}
__device__ __forceinline__ uint32_t cvt_h2(float lo, float hi) {
    uint32_t d;
    asm("cvt.rn.f16x2.f32 %0, %1, %2;" : "=r"(d) : "f"(hi), "f"(lo));
    return d;
}
__device__ __forceinline__ uint32_t ex2_h2(uint32_t a) {
    uint32_t d; asm("ex2.approx.f16x2 %0, %1;" : "=r"(d) : "r"(a)); return d;
}
// position of logical k (0..15) inside a permuted 16-group:
__device__ __forceinline__ int kperm(int k) {
    return (((k & 6) + (k >> 3)) << 1) + (k & 1);
}

// ---------------- K0: X1 = relu(x@W1+b1), prescaled (eta,phi), permuted X1t ----------------
__global__ void prep_kernel(const float* __restrict__ x, const float* __restrict__ W1,
                            const float* __restrict__ b1, const float* __restrict__ alpha_p) {
    int row = blockIdx.x * 4 + (threadIdx.x >> 6);
    int n = threadIdx.x & 63;
    float acc = b1[n];
#pragma unroll
    for (int k = 0; k < 7; k++) acc += x[row * 7 + k] * W1[k * NW + n];
    acc = fmaxf(acc, 0.0f);
    g_X1f[row * NW + n] = acc;
    int prow = (row & ~15) | kperm(row & 15);
    g_X1t[(size_t)n * N_NODES + prow] = __float2half(acc);
    if (n == 0) {
        const float L2E = 1.4426950408889634f;
        float sc = sqrtf(alpha_p[0] * L2E);
        g_eps[row] = make_float2(sc * x[row * 7 + 1], sc * x[row * 7 + 2]);
    }
}

// ---------------- fused GEMM: half2 E-args, f16 acc, Z via ones-MMA ----------------
// grid: 64 rtiles x 32 kq. Block 256 = 8 warps, each warp owns 16 rows.
__global__ __launch_bounds__(256, 6) void fused_gemm_kernel(int which,
                                                            const float* __restrict__ alpha_p) {
    extern __shared__ char smem[];
    __half* sB = reinterpret_cast<__half*>(smem);
    const __half* __restrict__ Xt = which ? g_X2t : g_X1t;

    int tid = threadIdx.x, lane = tid & 31, warp = tid >> 5;
    int rtile = blockIdx.x >> 5, kq = blockIdx.x & 31;
    int rbase = rtile * BM, kbeg = kq * KSLICE;

    const float L2E = 1.4426950408889634f;
    float sc = sqrtf(alpha_p[0] * L2E);
    const float C = 0.5287663729448977f;    // log2(log2 e)
    float wrapc = sc * 6.283185307179586f;  // scaled 2*pi

    // ---- stage B slice [64 n][256 k, permuted] via cp.async; j-pair table by STS ----
    uint32_t sb_base = smem_u32(smem);
    uint32_t* sJH = reinterpret_cast<uint32_t*>(smem + BSMEM);
    {
#pragma unroll
        for (int it = 0; it < 8; it++) {
            int ch = tid + it * 256;        // 2048 chunks of 16B
            int n = ch >> 5, kc = ch & 31;
            uint32_t dst = sb_base + (uint32_t)(n * BSTRIDE + kc * 8) * 2;
            cpa16(dst, Xt + (size_t)n * N_NODES + kbeg + kc * 8);
        }
        asm volatile("cp.async.commit_group;\n" ::: "memory");
        if (tid < 128) {
            float2 ja = g_eps[kbeg + tid * 2];
            float2 jb = g_eps[kbeg + tid * 2 + 1];
            sJH[tid * 2]     = cvt_h2(ja.x, jb.x);   // e-pair
            sJH[tid * 2 + 1] = cvt_h2(ja.y, jb.y);   // p-pair
        }
        asm volatile("cp.async.wait_group 0;\n" ::: "memory");
        __syncthreads();
    }

    int r = lane >> 2;
    int row0 = rbase + warp * 16 + r;
    float2 v0 = g_eps[row0];
    float2 v1 = g_eps[row0 + 8];
    __half2 er0b = __half2half2(__float2half(v0.x));
    __half2 pr0b = __half2half2(__float2half(v0.y));
    __half2 er1b = __half2half2(__float2half(v1.x));
    __half2 pr1b = __half2half2(__float2half(v1.y));
    __half2 wrap2 = __half2half2(__float2half(wrapc));
    __half2 C2 = __half2half2(__float2half(C));

    int c0 = (lane & 3) * 2;
    int ch = c0 >> 1;

    uint32_t acc[8][2];
#pragma unroll
    for (int nt = 0; nt < 8; nt++) { acc[nt][0] = 0u; acc[nt][1] = 0u; }
    float accZ[4] = {0.f, 0.f, 0.f, 0.f};
    const uint32_t BONE = 0x3C003C00u;      // half2(1,1)

    const __half* bwp = sB + (size_t)(lane >> 2) * BSTRIDE + c0 * 2;
    const uint2* sJ2 = reinterpret_cast<const uint2*>(sJH);

#pragma unroll 2
    for (int st = 0; st < NSTEP; st++) {
        uint2 j0 = sJ2[st * 8 + ch];        // cols c0, c0+1
        uint2 j1 = sJ2[st * 8 + ch + 4];    // cols c0+8, c0+9
        __half2 ej0 = *reinterpret_cast<__half2*>(&j0.x);
        __half2 pj0 = *reinterpret_cast<__half2*>(&j0.y);
        __half2 ej1 = *reinterpret_cast<__half2*>(&j1.x);
        __half2 pj1 = *reinterpret_cast<__half2*>(&j1.y);

        uint32_t a0, a1, a2, a3;
        {
            __half2 de = __hsub2(er0b, ej0);
            __half2 dpa = __habs2(__hsub2(pr0b, pj0));
            __half2 dpm = __hmin2(dpa, __hsub2(wrap2, dpa));
            __half2 t = __hfma2(de, de, __hmul2(dpm, dpm));
            __half2 arg = __hsub2(C2, t);
            a0 = ex2_h2(ex2_h2(*reinterpret_cast<uint32_t*>(&arg)));
        }
        {
            __half2 de = __hsub2(er1b, ej0);
            __half2 dpa = __habs2(__hsub2(pr1b, pj0));
            __half2 dpm = __hmin2(dpa, __hsub2(wrap2, dpa));
            __half2 t = __hfma2(de, de, __hmul2(dpm, dpm));
            __half2 arg = __hsub2(C2, t);
            a1 = ex2_h2(ex2_h2(*reinterpret_cast<uint32_t*>(&arg)));
        }
        {
            __half2 de = __hsub2(er0b, ej1);
            __half2 dpa = __habs2(__hsub2(pr0b, pj1));
            __half2 dpm = __hmin2(dpa, __hsub2(wrap2, dpa));
            __half2 t = __hfma2(de, de, __hmul2(dpm, dpm));
            __half2 arg = __hsub2(C2, t);
            a2 = ex2_h2(ex2_h2(*reinterpret_cast<uint32_t*>(&arg)));
        }
        {
            __half2 de = __hsub2(er1b, ej1);
            __half2 dpa = __habs2(__hsub2(pr1b, pj1));
            __half2 dpm = __hmin2(dpa, __hsub2(wrap2, dpa));
            __half2 t = __hfma2(de, de, __hmul2(dpm, dpm));
            __half2 arg = __hsub2(C2, t);
            a3 = ex2_h2(ex2_h2(*reinterpret_cast<uint32_t*>(&arg)));
        }

        // Z via ones-B MMA (fp32 accumulate, exact row sums)
        asm volatile(
            "mma.sync.aligned.m16n8k16.row.col.f32.f16.f16.f32 "
            "{%0,%1,%2,%3}, {%4,%5,%6,%7}, {%8,%9}, {%0,%1,%2,%3};"
            : "+f"(accZ[0]), "+f"(accZ[1]), "+f"(accZ[2]), "+f"(accZ[3])
            : "r"(a0), "r"(a1), "r"(a2), "r"(a3), "r"(BONE), "r"(BONE));

        const __half* bsp = bwp + st * 16;
#pragma unroll
        for (int nt = 0; nt < 8; nt++) {
            uint2 bb = *reinterpret_cast<const uint2*>(bsp + (size_t)nt * 8 * BSTRIDE);
            asm volatile(
                "mma.sync.aligned.m16n8k16.row.col.f16.f16.f16.f16 "
                "{%0,%1}, {%2,%3,%4,%5}, {%6,%7}, {%0,%1};"
                : "+r"(acc[nt][0]), "+r"(acc[nt][1])
                : "r"(a0), "r"(a1), "r"(a2), "r"(a3), "r"(bb.x), "r"(bb.y));
        }
    }

    // ---- Z partials: every lane in a quad holds identical col values ----
    if ((lane & 3) == 0) {
        g_Zp[kq][row0] = accZ[0];
        g_Zp[kq][row0 + 8] = accZ[2];
    }

    // ---- epilogue: acc already half2 partials ----
    uint32_t* Yp = g_Yph[kq];
    int cp = lane & 3;
#pragma unroll
    for (int nt = 0; nt < 8; nt++) {
        Yp[(size_t)row0 * 32 + nt * 4 + cp] = acc[nt][0];
        Yp[(size_t)(row0 + 8) * 32 + nt * 4 + cp] = acc[nt][1];
    }
}

// ---------------- mid: combine + V1=relu(Y@wt1+bs1) + X2=relu(V1@W2+b2) ----------------
// 256 blocks x 32 rows
#define MID_SMEM ((4096 * 2 + 2048 + 32) * 4)
__global__ __launch_bounds__(256) void mid_kernel(const float* __restrict__ wt1,
                                                  const float* __restrict__ bs1,
                                                  const float* __restrict__ W2,
                                                  const float* __restrict__ b2) {
    extern __shared__ float sm[];
    float* s_w1 = sm;
    float* s_w2 = sm + 4096;
    float* s_y  = sm + 8192;
    float* s_zi = sm + 8192 + 2048;
    int tid = threadIdx.x;
    int r0 = blockIdx.x * 32;

    for (int i = tid; i < 4096; i += 256) { s_w1[i] = wt1[i]; s_w2[i] = W2[i]; }
    if (tid < 32) {
        float zs = 0.f;
#pragma unroll
        for (int p = 0; p < SPLITK; p++) zs += g_Zp[p][r0 + tid];
        s_zi[tid] = 1.0f / zs;
    }
    __syncthreads();

    const float4* X4 = reinterpret_cast<const float4*>(g_X1f + (size_t)r0 * NW);
#pragma unroll
    for (int it = 0; it < 2; it++) {
        int i = tid + it * 256;             // 512 float4 = 32 rows x 16
        float4 v = make_float4(0.f, 0.f, 0.f, 0.f);
#pragma unroll
        for (int p = 0; p < SPLITK; p++) {
            uint2 u = reinterpret_cast<const uint2*>(g_Yph[p] + (size_t)r0 * 32)[i];
            float2 fa = __half22float2(*reinterpret_cast<__half2*>(&u.x));
            float2 fb = __half22float2(*reinterpret_cast<__half2*>(&u.y));
            v.x += fa.x; v.y += fa.y; v.z += fb.x; v.w += fb.y;
        }
        float zi = s_zi[i >> 4];
        float4 xv = X4[i];
        reinterpret_cast<float4*>(s_y)[i] =
            make_float4(fmaf(v.x, zi, xv.x), fmaf(v.y, zi, xv.y),
                        fmaf(v.z, zi, xv.z), fmaf(v.w, zi, xv.w));
    }
    __syncthreads();

    int cgp = tid & 15, rg = tid >> 4;
    int c0 = cgp * 4, rl0 = rg * 2;
    float bsv = bs1[0];
    float acc[2][4];
#pragma unroll
    for (int rr = 0; rr < 2; rr++)
#pragma unroll
        for (int c = 0; c < 4; c++) acc[rr][c] = bsv;
#pragma unroll 8
    for (int k = 0; k < 64; k++) {
        float4 w = reinterpret_cast<const float4*>(s_w1 + k * 64)[cgp];
#pragma unroll
        for (int rr = 0; rr < 2; rr++) {
            float y = s_y[(rl0 + rr) * 64 + k];
            acc[rr][0] = fmaf(y, w.x, acc[rr][0]);
            acc[rr][1] = fmaf(y, w.y, acc[rr][1]);
            acc[rr][2] = fmaf(y, w.z, acc[rr][2]);
            acc[rr][3] = fmaf(y, w.w, acc[rr][3]);
        }
    }
    __syncthreads();
#pragma unroll
    for (int rr = 0; rr < 2; rr++)
        reinterpret_cast<float4*>(s_y + (rl0 + rr) * 64)[cgp] =
            make_float4(fmaxf(acc[rr][0], 0.f), fmaxf(acc[rr][1], 0.f),
                        fmaxf(acc[rr][2], 0.f), fmaxf(acc[rr][3], 0.f));
    __syncthreads();

    float4 bz = *reinterpret_cast<const float4*>(b2 + c0);
#pragma unroll
    for (int rr = 0; rr < 2; rr++) { acc[rr][0] = bz.x; acc[rr][1] = bz.y; acc[rr][2] = bz.z; acc[rr][3] = bz.w; }
#pragma unroll 8
    for (int k = 0; k < 64; k++) {
        float4 w = reinterpret_cast<const float4*>(s_w2 + k * 64)[cgp];
#pragma unroll
        for (int rr = 0; rr < 2; rr++) {
            float y = s_y[(rl0 + rr) * 64 + k];
            acc[rr][0] = fmaf(y, w.x, acc[rr][0]);
            acc[rr][1] = fmaf(y, w.y, acc[rr][1]);
            acc[rr][2] = fmaf(y, w.z, acc[rr][2]);
            acc[rr][3] = fmaf(y, w.w, acc[rr][3]);
        }
    }
#pragma unroll
    for (int rr = 0; rr < 2; rr++)
#pragma unroll
        for (int c = 0; c < 4; c++) acc[rr][c] = fmaxf(acc[rr][c], 0.f);

#pragma unroll
    for (int rr = 0; rr < 2; rr++)
        *reinterpret_cast<float4*>(g_X2f + (size_t)(r0 + rl0 + rr) * NW + c0) =
            make_float4(acc[rr][0], acc[rr][1], acc[rr][2], acc[rr][3]);

    // permuted transposed write: rows rl0, rl0+1 are an even pair -> adjacent after perm
    {
        int base_row = r0 + rl0;
        int grp = base_row & ~15;
        int p0 = kperm(base_row & 15);
#pragma unroll
        for (int c = 0; c < 4; c++) {
            __half2 h01 = __floats2half2_rn(acc[0][c], acc[1][c]);
            __half* bp = g_X2t + (size_t)(c0 + c) * N_NODES + grp;
            *reinterpret_cast<__half2*>(bp + p0) = h01;
        }
    }
}

// ---------------- last: combine + V2=relu(Y@wt2+bs2) + column partial sums ----------------
#define LAST_SMEM ((4096 + 2048 + 32 + 1024) * 4)
__global__ __launch_bounds__(256) void last_kernel(const float* __restrict__ wt2,
                                                   const float* __restrict__ bs2) {
    extern __shared__ float sm[];
    float* s_w  = sm;
    float* s_y  = sm + 4096;
    float* s_zi = sm + 4096 + 2048;
    float* s_part = s_zi + 32;
    int tid = threadIdx.x;
    int r0 = blockIdx.x * 32;

    for (int i = tid; i < 4096; i += 256) s_w[i] = wt2[i];
    if (tid < 32) {
        float zs = 0.f;
#pragma unroll
        for (int p = 0; p < SPLITK; p++) zs += g_Zp[p][r0 + tid];
        s_zi[tid] = 1.0f / zs;
    }
    __syncthreads();

    const float4* X4 = reinterpret_cast<const float4*>(g_X2f + (size_t)r0 * NW);
#pragma unroll
    for (int it = 0; it < 2; it++) {
        int i = tid + it * 256;
        float4 v = make_float4(0.f, 0.f, 0.f, 0.f);
#pragma unroll
        for (int p = 0; p < SPLITK; p++) {
            uint2 u = reinterpret_cast<const uint2*>(g_Yph[p] + (size_t)r0 * 32)[i];
            float2 fa = __half22float2(*reinterpret_cast<__half2*>(&u.x));
            float2 fb = __half22float2(*reinterpret_cast<__half2*>(&u.y));
            v.x += fa.x; v.y += fa.y; v.z += fb.x; v.w += fb.y;
        }
        float zi = s_zi[i >> 4];
        float4 xv = X4[i];
        reinterpret_cast<float4*>(s_y)[i] =
            make_float4(fmaf(v.x, zi, xv.x), fmaf(v.y, zi, xv.y),
                        fmaf(v.z, zi, xv.z), fmaf(v.w, zi, xv.w));
    }
    __syncthreads();

    int cgp = tid & 15, rg = tid >> 4;
    int c0 = cgp * 4, rl0 = rg * 2;
    float bv = bs2[0];
    float acc[2][4];
#pragma unroll
    for (int rr = 0; rr < 2; rr++)
#pragma unroll
        for (int c = 0; c < 4; c++) acc[rr][c] = bv;
#pragma unroll 8
    for (int k = 0; k < 64; k++) {
        float4 w = reinterpret_cast<const float4*>(s_w + k * 64)[cgp];
#pragma unroll
        for (int rr = 0; rr < 2; rr++) {
            float y = s_y[(rl0 + rr) * 64 + k];
            acc[rr][0] = fmaf(y, w.x, acc[rr][0]);
            acc[rr][1] = fmaf(y, w.y, acc[rr][1]);
            acc[rr][2] = fmaf(y, w.z, acc[rr][2]);
            acc[rr][3] = fmaf(y, w.w, acc[rr][3]);
        }
    }
#pragma unroll
    for (int c = 0; c < 4; c++) {
        float cs = fmaxf(acc[0][c], 0.f) + fmaxf(acc[1][c], 0.f);
        s_part[rg * 64 + c0 + c] = cs;
    }
    __syncthreads();
    if (tid < 64) {
        float t = 0.f;
#pragma unroll
        for (int g = 0; g < 16; g++) t += s_part[g * 64 + tid];
        g_sp[blockIdx.x * NW + tid] = t;
    }
}

// ---------------- final: out = sigmoid(s@Wl + bl) ----------------
__global__ void final_kernel(const float* __restrict__ Wl, const float* __restrict__ bl,
                             float* __restrict__ out) {
    int tid = threadIdx.x;             // 256 threads
    int n = tid & 63, g = tid >> 6;    // 4 chunks of 64 rows
    float s = 0.0f;
    for (int b = g * 64; b < (g + 1) * 64; b++) s += g_sp[b * NW + n];
    __shared__ float sh[256];
    sh[tid] = s;
    __syncthreads();
    if (tid < 64) {
        float t = (sh[tid] + sh[tid + 64] + sh[tid + 128] + sh[tid + 192]) * Wl[tid];
        sh[tid] = t;
    }
    __syncthreads();
    if (tid < 32) {
        float t = sh[tid] + sh[tid + 32];
        for (int o = 16; o; o >>= 1) t += __shfl_down_sync(0xffffffffu, t, o);
        if (tid == 0) out[0] = 1.0f / (1.0f + expf(-(t + bl[0])));
    }
}

// ---------------- launch ----------------
extern "C" void kernel_launch(void* const* d_in, const int* in_sizes, int n_in,
                              void* d_out, int out_size) {
    (void)in_sizes; (void)n_in; (void)out_size;
    const float* x     = (const float*)d_in[0];
    const float* alpha = (const float*)d_in[1];
    const float* W1    = (const float*)d_in[2];
    const float* b1    = (const float*)d_in[3];
    const float* wt1   = (const float*)d_in[4];
    const float* bs1   = (const float*)d_in[5];
    const float* W2    = (const float*)d_in[6];
    const float* b2    = (const float*)d_in[7];
    const float* wt2   = (const float*)d_in[8];
    const float* bs2   = (const float*)d_in[9];
    const float* Wl    = (const float*)d_in[10];
    const float* bl    = (const float*)d_in[11];
    float* out = (float*)d_out;

    cudaFuncSetAttribute(fused_gemm_kernel, cudaFuncAttributeMaxDynamicSharedMemorySize, FUSED_SMEM);
    cudaFuncSetAttribute(mid_kernel, cudaFuncAttributeMaxDynamicSharedMemorySize, MID_SMEM);
    cudaFuncSetAttribute(last_kernel, cudaFuncAttributeMaxDynamicSharedMemorySize, LAST_SMEM);

    prep_kernel<<<2048, 256>>>(x, W1, b1, alpha);

    fused_gemm_kernel<<<2048, 256, FUSED_SMEM>>>(0, alpha);
    mid_kernel<<<256, 256, MID_SMEM>>>(wt1, bs1, W2, b2);

    fused_gemm_kernel<<<2048, 256, FUSED_SMEM>>>(1, alpha);
    last_kernel<<<256, 256, LAST_SMEM>>>(wt2, bs2);

    final_kernel<<<1, 256>>>(Wl, bl, out);
}

// round 15
// speedup vs baseline: 1.5757x; 1.1078x over previous
#include <cuda_runtime.h>
#include <cuda_fp16.h>
#include <math.h>
#include <stdint.h>

#define N_NODES 8192
#define NW 64
#define SPLITK 32
#define KSLICE (N_NODES / SPLITK)   // 256
#define BM 256
#define NSTEP (KSLICE / 16)         // 16 k16-steps
#define BSTRIDE 272                 // halfs per B smem row (256 + 16) -> 8-bank shift/row
#define BSMEM (64 * BSTRIDE * 2)    // 34816 bytes
#define FUSED_SMEM (BSMEM + 1024)   // + 128 j-pairs * 8B (half2 e-pair, p-pair)

// ---------------- scratch (device globals) ----------------
__device__ float    g_Zp[SPLITK][N_NODES];
__device__ float    g_X1f[N_NODES * NW];
__device__ __half   g_X1t[NW * N_NODES];               // k-permuted [n][perm(row)]
__device__ float    g_X2f[N_NODES * NW];
__device__ __half   g_X2t[NW * N_NODES];               // k-permuted
__device__ uint32_t g_Yph[SPLITK][N_NODES * 32];       // half2 split-K GEMM partials (32MB)
__device__ __align__(16) float2 g_eps[N_NODES];        // prescaled (sc*eta, sc*phi)
__device__ float    g_sp[256 * NW];

__device__ __forceinline__ void cpa16(uint32_t dst, const void* src) {
    asm volatile("cp.async.cg.shared.global [%0], [%1], 16;\n" :: "r"(dst), "l"(src));
}
__device__ __forceinline__ uint32_t smem_u32(const void* p) {
    uint32_t a;
    asm("{ .reg .u64 t; cvta.to.shared.u64 t, %1; cvt.u32.u64 %0, t; }" : "=r"(a) : "l"(p));
    return a;
}
__device__ __forceinline__ uint32_t cvt_h2(float lo, float hi) {
    uint32_t d;
    asm("cvt.rn.f16x2.f32 %0, %1, %2;" : "=r"(d) : "f"(hi), "f"(lo));
    return d;
}
__device__ __forceinline__ uint32_t ex2_h2(uint32_t a) {
    uint32_t d; asm("ex2.approx.f16x2 %0, %1;" : "=r"(d) : "r"(a)); return d;
}
// position of logical k (0..15) inside a permuted 16-group:
__device__ __forceinline__ int kperm(int k) {
    return (((k & 6) + (k >> 3)) << 1) + (k & 1);
}
// E fragment: exp(exp(-(de^2+dp^2))) in f16x2, given broadcast row coords and j pair
__device__ __forceinline__ uint32_t efrag(__half2 erb, __half2 prb, __half2 ej, __half2 pj,
                                          __half2 wrap2, __half2 C2) {
    __half2 de = __hsub2(erb, ej);
    __half2 dpa = __habs2(__hsub2(prb, pj));
    __half2 dpm = __hmin2(dpa, __hsub2(wrap2, dpa));
    __half2 t = __hfma2(de, de, __hmul2(dpm, dpm));
    __half2 arg = __hsub2(C2, t);
    return ex2_h2(ex2_h2(*reinterpret_cast<uint32_t*>(&arg)));
}

// ---------------- K0: X1 = relu(x@W1+b1), prescaled (eta,phi), permuted X1t ----------------
__global__ void prep_kernel(const float* __restrict__ x, const float* __restrict__ W1,
                            const float* __restrict__ b1, const float* __restrict__ alpha_p) {
    int row = blockIdx.x * 4 + (threadIdx.x >> 6);
    int n = threadIdx.x & 63;
    float acc = b1[n];
#pragma unroll
    for (int k = 0; k < 7; k++) acc += x[row * 7 + k] * W1[k * NW + n];
    acc = fmaxf(acc, 0.0f);
    g_X1f[row * NW + n] = acc;
    int prow = (row & ~15) | kperm(row & 15);
    g_X1t[(size_t)n * N_NODES + prow] = __float2half(acc);
    if (n == 0) {
        const float L2E = 1.4426950408889634f;
        float sc = sqrtf(alpha_p[0] * L2E);
        g_eps[row] = make_float2(sc * x[row * 7 + 1], sc * x[row * 7 + 2]);
    }
}

// ---------------- fused GEMM: 2 A-sets per warp share each B fragment ----------------
// grid: 32 rtiles x 32 kq. Block 256 = 8 warps, each warp owns 32 rows (2 A-sets).
__global__ __launch_bounds__(256, 3) void fused_gemm_kernel(int which,
                                                            const float* __restrict__ alpha_p) {
    extern __shared__ char smem[];
    __half* sB = reinterpret_cast<__half*>(smem);
    const __half* __restrict__ Xt = which ? g_X2t : g_X1t;

    int tid = threadIdx.x, lane = tid & 31, warp = tid >> 5;
    int rtile = blockIdx.x >> 5, kq = blockIdx.x & 31;
    int rbase = rtile * BM, kbeg = kq * KSLICE;

    const float L2E = 1.4426950408889634f;
    float sc = sqrtf(alpha_p[0] * L2E);
    const float C = 0.5287663729448977f;    // log2(log2 e)
    float wrapc = sc * 6.283185307179586f;  // scaled 2*pi

    // ---- stage B slice [64 n][256 k, permuted] via cp.async; j-pair table by STS ----
    uint32_t sb_base = smem_u32(smem);
    uint32_t* sJH = reinterpret_cast<uint32_t*>(smem + BSMEM);
    {
#pragma unroll
        for (int it = 0; it < 8; it++) {
            int ch = tid + it * 256;        // 2048 chunks of 16B
            int n = ch >> 5, kc = ch & 31;
            uint32_t dst = sb_base + (uint32_t)(n * BSTRIDE + kc * 8) * 2;
            cpa16(dst, Xt + (size_t)n * N_NODES + kbeg + kc * 8);
        }
        asm volatile("cp.async.commit_group;\n" ::: "memory");
        if (tid < 128) {
            float2 ja = g_eps[kbeg + tid * 2];
            float2 jb = g_eps[kbeg + tid * 2 + 1];
            sJH[tid * 2]     = cvt_h2(ja.x, jb.x);   // e-pair
            sJH[tid * 2 + 1] = cvt_h2(ja.y, jb.y);   // p-pair
        }
        asm volatile("cp.async.wait_group 0;\n" ::: "memory");
        __syncthreads();
    }

    int r = lane >> 2;
    // per-set row coords: set s covers rows warp*32 + s*16 + {r, r+8}
    __half2 erb[2][2], prb[2][2];
#pragma unroll
    for (int s = 0; s < 2; s++) {
        float2 v0 = g_eps[rbase + warp * 32 + s * 16 + r];
        float2 v1 = g_eps[rbase + warp * 32 + s * 16 + r + 8];
        erb[s][0] = __half2half2(__float2half(v0.x));
        prb[s][0] = __half2half2(__float2half(v0.y));
        erb[s][1] = __half2half2(__float2half(v1.x));
        prb[s][1] = __half2half2(__float2half(v1.y));
    }
    __half2 wrap2 = __half2half2(__float2half(wrapc));
    __half2 C2 = __half2half2(__float2half(C));

    int c0 = (lane & 3) * 2;
    int ch = c0 >> 1;

    uint32_t acc[2][8][2];
#pragma unroll
    for (int s = 0; s < 2; s++)
#pragma unroll
        for (int nt = 0; nt < 8; nt++) { acc[s][nt][0] = 0u; acc[s][nt][1] = 0u; }
    float accZ[2][4];
#pragma unroll
    for (int s = 0; s < 2; s++)
#pragma unroll
        for (int q = 0; q < 4; q++) accZ[s][q] = 0.f;
    const uint32_t BONE = 0x3C003C00u;      // half2(1,1)

    const __half* bwp = sB + (size_t)(lane >> 2) * BSTRIDE + c0 * 2;
    const uint2* sJ2 = reinterpret_cast<const uint2*>(sJH);

#pragma unroll 1
    for (int st = 0; st < NSTEP; st++) {
        uint2 j0 = sJ2[st * 8 + ch];        // cols c0, c0+1
        uint2 j1 = sJ2[st * 8 + ch + 4];    // cols c0+8, c0+9
        __half2 ej0 = *reinterpret_cast<__half2*>(&j0.x);
        __half2 pj0 = *reinterpret_cast<__half2*>(&j0.y);
        __half2 ej1 = *reinterpret_cast<__half2*>(&j1.x);
        __half2 pj1 = *reinterpret_cast<__half2*>(&j1.y);

        uint32_t A[2][4];
#pragma unroll
        for (int s = 0; s < 2; s++) {
            A[s][0] = efrag(erb[s][0], prb[s][0], ej0, pj0, wrap2, C2);
            A[s][1] = efrag(erb[s][1], prb[s][1], ej0, pj0, wrap2, C2);
            A[s][2] = efrag(erb[s][0], prb[s][0], ej1, pj1, wrap2, C2);
            A[s][3] = efrag(erb[s][1], prb[s][1], ej1, pj1, wrap2, C2);
            // Z via ones-B MMA (fp32 accumulate, exact row sums)
            asm volatile(
                "mma.sync.aligned.m16n8k16.row.col.f32.f16.f16.f32 "
                "{%0,%1,%2,%3}, {%4,%5,%6,%7}, {%8,%9}, {%0,%1,%2,%3};"
                : "+f"(accZ[s][0]), "+f"(accZ[s][1]), "+f"(accZ[s][2]), "+f"(accZ[s][3])
                : "r"(A[s][0]), "r"(A[s][1]), "r"(A[s][2]), "r"(A[s][3]),
                  "r"(BONE), "r"(BONE));
        }

        const __half* bsp = bwp + st * 16;
#pragma unroll
        for (int nt = 0; nt < 8; nt++) {
            uint2 bb = *reinterpret_cast<const uint2*>(bsp + (size_t)nt * 8 * BSTRIDE);
            asm volatile(
                "mma.sync.aligned.m16n8k16.row.col.f16.f16.f16.f16 "
                "{%0,%1}, {%2,%3,%4,%5}, {%6,%7}, {%0,%1};"
                : "+r"(acc[0][nt][0]), "+r"(acc[0][nt][1])
                : "r"(A[0][0]), "r"(A[0][1]), "r"(A[0][2]), "r"(A[0][3]),
                  "r"(bb.x), "r"(bb.y));
            asm volatile(
                "mma.sync.aligned.m16n8k16.row.col.f16.f16.f16.f16 "
                "{%0,%1}, {%2,%3,%4,%5}, {%6,%7}, {%0,%1};"
                : "+r"(acc[1][nt][0]), "+r"(acc[1][nt][1])
                : "r"(A[1][0]), "r"(A[1][1]), "r"(A[1][2]), "r"(A[1][3]),
                  "r"(bb.x), "r"(bb.y));
        }
    }

    // ---- Z partials + epilogue per set ----
    int cp = lane & 3;
#pragma unroll
    for (int s = 0; s < 2; s++) {
        int row0 = rbase + warp * 32 + s * 16 + r;
        if (cp == 0) {
            g_Zp[kq][row0] = accZ[s][0];
            g_Zp[kq][row0 + 8] = accZ[s][2];
        }
        uint32_t* Yp = g_Yph[kq];
#pragma unroll
        for (int nt = 0; nt < 8; nt++) {
            Yp[(size_t)row0 * 32 + nt * 4 + cp] = acc[s][nt][0];
            Yp[(size_t)(row0 + 8) * 32 + nt * 4 + cp] = acc[s][nt][1];
        }
    }
}

// ---------------- mid: combine + V1=relu(Y@wt1+bs1) + X2=relu(V1@W2+b2) ----------------
// 256 blocks x 32 rows
#define MID_SMEM ((4096 * 2 + 2048 + 32) * 4)
__global__ __launch_bounds__(256) void mid_kernel(const float* __restrict__ wt1,
                                                  const float* __restrict__ bs1,
                                                  const float* __restrict__ W2,
                                                  const float* __restrict__ b2) {
    extern __shared__ float sm[];
    float* s_w1 = sm;
    float* s_w2 = sm + 4096;
    float* s_y  = sm + 8192;
    float* s_zi = sm + 8192 + 2048;
    int tid = threadIdx.x;
    int r0 = blockIdx.x * 32;

    for (int i = tid; i < 4096; i += 256) { s_w1[i] = wt1[i]; s_w2[i] = W2[i]; }
    if (tid < 32) {
        float zs = 0.f;
#pragma unroll
        for (int p = 0; p < SPLITK; p++) zs += g_Zp[p][r0 + tid];
        s_zi[tid] = 1.0f / zs;
    }
    __syncthreads();

    const float4* X4 = reinterpret_cast<const float4*>(g_X1f + (size_t)r0 * NW);
#pragma unroll
    for (int it = 0; it < 2; it++) {
        int i = tid + it * 256;             // 512 float4 = 32 rows x 16
        float4 v = make_float4(0.f, 0.f, 0.f, 0.f);
#pragma unroll
        for (int p = 0; p < SPLITK; p++) {
            uint2 u = reinterpret_cast<const uint2*>(g_Yph[p] + (size_t)r0 * 32)[i];
            float2 fa = __half22float2(*reinterpret_cast<__half2*>(&u.x));
            float2 fb = __half22float2(*reinterpret_cast<__half2*>(&u.y));
            v.x += fa.x; v.y += fa.y; v.z += fb.x; v.w += fb.y;
        }
        float zi = s_zi[i >> 4];
        float4 xv = X4[i];
        reinterpret_cast<float4*>(s_y)[i] =
            make_float4(fmaf(v.x, zi, xv.x), fmaf(v.y, zi, xv.y),
                        fmaf(v.z, zi, xv.z), fmaf(v.w, zi, xv.w));
    }
    __syncthreads();

    int cgp = tid & 15, rg = tid >> 4;
    int c0 = cgp * 4, rl0 = rg * 2;
    float bsv = bs1[0];
    float acc[2][4];
#pragma unroll
    for (int rr = 0; rr < 2; rr++)
#pragma unroll
        for (int c = 0; c < 4; c++) acc[rr][c] = bsv;
#pragma unroll 8
    for (int k = 0; k < 64; k++) {
        float4 w = reinterpret_cast<const float4*>(s_w1 + k * 64)[cgp];
#pragma unroll
        for (int rr = 0; rr < 2; rr++) {
            float y = s_y[(rl0 + rr) * 64 + k];
            acc[rr][0] = fmaf(y, w.x, acc[rr][0]);
            acc[rr][1] = fmaf(y, w.y, acc[rr][1]);
            acc[rr][2] = fmaf(y, w.z, acc[rr][2]);
            acc[rr][3] = fmaf(y, w.w, acc[rr][3]);
        }
    }
    __syncthreads();
#pragma unroll
    for (int rr = 0; rr < 2; rr++)
        reinterpret_cast<float4*>(s_y + (rl0 + rr) * 64)[cgp] =
            make_float4(fmaxf(acc[rr][0], 0.f), fmaxf(acc[rr][1], 0.f),
                        fmaxf(acc[rr][2], 0.f), fmaxf(acc[rr][3], 0.f));
    __syncthreads();

    float4 bz = *reinterpret_cast<const float4*>(b2 + c0);
#pragma unroll
    for (int rr = 0; rr < 2; rr++) { acc[rr][0] = bz.x; acc[rr][1] = bz.y; acc[rr][2] = bz.z; acc[rr][3] = bz.w; }
#pragma unroll 8
    for (int k = 0; k < 64; k++) {
        float4 w = reinterpret_cast<const float4*>(s_w2 + k * 64)[cgp];
#pragma unroll
        for (int rr = 0; rr < 2; rr++) {
            float y = s_y[(rl0 + rr) * 64 + k];
            acc[rr][0] = fmaf(y, w.x, acc[rr][0]);
            acc[rr][1] = fmaf(y, w.y, acc[rr][1]);
            acc[rr][2] = fmaf(y, w.z, acc[rr][2]);
            acc[rr][3] = fmaf(y, w.w, acc[rr][3]);
        }
    }
#pragma unroll
    for (int rr = 0; rr < 2; rr++)
#pragma unroll
        for (int c = 0; c < 4; c++) acc[rr][c] = fmaxf(acc[rr][c], 0.f);

#pragma unroll
    for (int rr = 0; rr < 2; rr++)
        *reinterpret_cast<float4*>(g_X2f + (size_t)(r0 + rl0 + rr) * NW + c0) =
            make_float4(acc[rr][0], acc[rr][1], acc[rr][2], acc[rr][3]);

    // permuted transposed write: rows rl0, rl0+1 are an even pair -> adjacent after perm
    {
        int base_row = r0 + rl0;
        int grp = base_row & ~15;
        int p0 = kperm(base_row & 15);
#pragma unroll
        for (int c = 0; c < 4; c++) {
            __half2 h01 = __floats2half2_rn(acc[0][c], acc[1][c]);
            __half* bp = g_X2t + (size_t)(c0 + c) * N_NODES + grp;
            *reinterpret_cast<__half2*>(bp + p0) = h01;
        }
    }
}

// ---------------- last: combine + V2=relu(Y@wt2+bs2) + column partial sums ----------------
#define LAST_SMEM ((4096 + 2048 + 32 + 1024) * 4)
__global__ __launch_bounds__(256) void last_kernel(const float* __restrict__ wt2,
                                                   const float* __restrict__ bs2) {
    extern __shared__ float sm[];
    float* s_w  = sm;
    float* s_y  = sm + 4096;
    float* s_zi = sm + 4096 + 2048;
    float* s_part = s_zi + 32;
    int tid = threadIdx.x;
    int r0 = blockIdx.x * 32;

    for (int i = tid; i < 4096; i += 256) s_w[i] = wt2[i];
    if (tid < 32) {
        float zs = 0.f;
#pragma unroll
        for (int p = 0; p < SPLITK; p++) zs += g_Zp[p][r0 + tid];
        s_zi[tid] = 1.0f / zs;
    }
    __syncthreads();

    const float4* X4 = reinterpret_cast<const float4*>(g_X2f + (size_t)r0 * NW);
#pragma unroll
    for (int it = 0; it < 2; it++) {
        int i = tid + it * 256;
        float4 v = make_float4(0.f, 0.f, 0.f, 0.f);
#pragma unroll
        for (int p = 0; p < SPLITK; p++) {
            uint2 u = reinterpret_cast<const uint2*>(g_Yph[p] + (size_t)r0 * 32)[i];
            float2 fa = __half22float2(*reinterpret_cast<__half2*>(&u.x));
            float2 fb = __half22float2(*reinterpret_cast<__half2*>(&u.y));
            v.x += fa.x; v.y += fa.y; v.z += fb.x; v.w += fb.y;
        }
        float zi = s_zi[i >> 4];
        float4 xv = X4[i];
        reinterpret_cast<float4*>(s_y)[i] =
            make_float4(fmaf(v.x, zi, xv.x), fmaf(v.y, zi, xv.y),
                        fmaf(v.z, zi, xv.z), fmaf(v.w, zi, xv.w));
    }
    __syncthreads();

    int cgp = tid & 15, rg = tid >> 4;
    int c0 = cgp * 4, rl0 = rg * 2;
    float bv = bs2[0];
    float acc[2][4];
#pragma unroll
    for (int rr = 0; rr < 2; rr++)
#pragma unroll
        for (int c = 0; c < 4; c++) acc[rr][c] = bv;
#pragma unroll 8
    for (int k = 0; k < 64; k++) {
        float4 w = reinterpret_cast<const float4*>(s_w + k * 64)[cgp];
#pragma unroll
        for (int rr = 0; rr < 2; rr++) {
            float y = s_y[(rl0 + rr) * 64 + k];
            acc[rr][0] = fmaf(y, w.x, acc[rr][0]);
            acc[rr][1] = fmaf(y, w.y, acc[rr][1]);
            acc[rr][2] = fmaf(y, w.z, acc[rr][2]);
            acc[rr][3] = fmaf(y, w.w, acc[rr][3]);
        }
    }
#pragma unroll
    for (int c = 0; c < 4; c++) {
        float cs = fmaxf(acc[0][c], 0.f) + fmaxf(acc[1][c], 0.f);
        s_part[rg * 64 + c0 + c] = cs;
    }
    __syncthreads();
    if (tid < 64) {
        float t = 0.f;
#pragma unroll
        for (int g = 0; g < 16; g++) t += s_part[g * 64 + tid];
        g_sp[blockIdx.x * NW + tid] = t;
    }
}

// ---------------- final: out = sigmoid(s@Wl + bl) ----------------
__global__ void final_kernel(const float* __restrict__ Wl, const float* __restrict__ bl,
                             float* __restrict__ out) {
    int tid = threadIdx.x;             // 256 threads
    int n = tid & 63, g = tid >> 6;    // 4 chunks of 64 rows
    float s = 0.0f;
    for (int b = g * 64; b < (g + 1) * 64; b++) s += g_sp[b * NW + n];
    __shared__ float sh[256];
    sh[tid] = s;
    __syncthreads();
    if (tid < 64) {
        float t = (sh[tid] + sh[tid + 64] + sh[tid + 128] + sh[tid + 192]) * Wl[tid];
        sh[tid] = t;
    }
    __syncthreads();
    if (tid < 32) {
        float t = sh[tid] + sh[tid + 32];
        for (int o = 16; o; o >>= 1) t += __shfl_down_sync(0xffffffffu, t, o);
        if (tid == 0) out[0] = 1.0f / (1.0f + expf(-(t + bl[0])));
    }
}

// ---------------- launch ----------------
extern "C" void kernel_launch(void* const* d_in, const int* in_sizes, int n_in,
                              void* d_out, int out_size) {
    (void)in_sizes; (void)n_in; (void)out_size;
    const float* x     = (const float*)d_in[0];
    const float* alpha = (const float*)d_in[1];
    const float* W1    = (const float*)d_in[2];
    const float* b1    = (const float*)d_in[3];
    const float* wt1   = (const float*)d_in[4];
    const float* bs1   = (const float*)d_in[5];
    const float* W2    = (const float*)d_in[6];
    const float* b2    = (const float*)d_in[7];
    const float* wt2   = (const float*)d_in[8];
    const float* bs2   = (const float*)d_in[9];
    const float* Wl    = (const float*)d_in[10];
    const float* bl    = (const float*)d_in[11];
    float* out = (float*)d_out;

    cudaFuncSetAttribute(fused_gemm_kernel, cudaFuncAttributeMaxDynamicSharedMemorySize, FUSED_SMEM);
    cudaFuncSetAttribute(mid_kernel, cudaFuncAttributeMaxDynamicSharedMemorySize, MID_SMEM);
    cudaFuncSetAttribute(last_kernel, cudaFuncAttributeMaxDynamicSharedMemorySize, LAST_SMEM);

    prep_kernel<<<2048, 256>>>(x, W1, b1, alpha);

    fused_gemm_kernel<<<1024, 256, FUSED_SMEM>>>(0, alpha);
    mid_kernel<<<256, 256, MID_SMEM>>>(wt1, bs1, W2, b2);

    fused_gemm_kernel<<<1024, 256, FUSED_SMEM>>>(1, alpha);
    last_kernel<<<256, 256, LAST_SMEM>>>(wt2, bs2);

    final_kernel<<<1, 256>>>(Wl, bl, out);
}